// round 13
// baseline (speedup 1.0000x reference)
#include <cuda_runtime.h>
#include <cstdint>

#define BB 16
#define NN 1024
#define FIN 64
#define HH 256

// ---------------- scratch (no allocs allowed) ----------------
__device__ float g_x[BB * NN * HH];   // 16 MB
__device__ float g_h[BB * NN * HH];   // 16 MB
__device__ float g_s1[BB * NN];
__device__ float g_s2[BB * NN];
__device__ uint32_t g_mask[BB * NN * (NN / 32)];   // 2 MB bit-packed adj
__device__ float g_pool[BB * 8 * 2 * HH];          // pooling partials

typedef unsigned long long u64;

__device__ __forceinline__ u64 pack2(float x) {
    u64 r; asm("mov.b64 %0, {%1, %1};" : "=l"(r) : "f"(x)); return r;
}
__device__ __forceinline__ void ffma2(u64& d, u64 a, u64 b) {
    asm("fma.rn.f32x2 %0, %1, %2, %0;" : "+l"(d) : "l"(a), "l"(b));
}
__device__ __forceinline__ float2 unpack2(u64 v) {
    float2 r; asm("mov.b64 {%0, %1}, %2;" : "=f"(r.x), "=f"(r.y) : "l"(v)); return r;
}
__device__ __forceinline__ float leaky(float x) { return x >= 0.f ? x : 0.2f * x; }

// ============================================================================
// pack_adj: adj float(0/1)[B*N*N] -> bitmask (1 bit per entry)
// ============================================================================
__global__ __launch_bounds__(256) void pack_adj_kernel(
    const float* __restrict__ adj, uint32_t* __restrict__ mask)
{
    const int idx = blockIdx.x * 256 + threadIdx.x;
    const float v = adj[idx];
    const unsigned bal = __ballot_sync(0xffffffffu, v > 0.f);
    if ((threadIdx.x & 31) == 0) mask[idx >> 5] = bal;
}

// ============================================================================
// embed: out[M,256] = nf[M,64] @ W[64,256] + b
// ============================================================================
__global__ __launch_bounds__(128) void embed_kernel(
    const float* __restrict__ nf, const float* __restrict__ W,
    const float* __restrict__ bias, float* __restrict__ out)
{
    __shared__ float xs[4 * FIN * 4];
    const int row0 = blockIdx.x * 16;
    const int tid = threadIdx.x;

#pragma unroll
    for (int it = 0; it < 2; it++) {
        int idx = it * 128 + tid;
        int g = idx >> 6, k = idx & 63;
        float4 v;
        v.x = nf[(size_t)(row0 + 4 * g + 0) * FIN + k];
        v.y = nf[(size_t)(row0 + 4 * g + 1) * FIN + k];
        v.z = nf[(size_t)(row0 + 4 * g + 2) * FIN + k];
        v.w = nf[(size_t)(row0 + 4 * g + 3) * FIN + k];
        *(float4*)(xs + g * (FIN * 4) + k * 4) = v;
    }
    __syncthreads();

    u64 accA[8], accB[8];
#pragma unroll
    for (int p = 0; p < 8; p++) { accA[p] = 0ULL; accB[p] = 0ULL; }

    const int c = tid;
    float wA[4], wB[4];
#pragma unroll
    for (int u = 0; u < 4; u++) { wA[u] = W[u * HH + c]; wB[u] = W[u * HH + c + 128]; }

    for (int kt = 0; kt < FIN; kt += 4) {
        float cAv[4], cBv[4];
#pragma unroll
        for (int u = 0; u < 4; u++) { cAv[u] = wA[u]; cBv[u] = wB[u]; }
        if (kt + 4 < FIN) {
#pragma unroll
            for (int u = 0; u < 4; u++) {
                wA[u] = W[(kt + 4 + u) * HH + c];
                wB[u] = W[(kt + 4 + u) * HH + c + 128];
            }
        }
#pragma unroll
        for (int u = 0; u < 4; u++) {
            int k = kt + u;
            u64 h2a = pack2(cAv[u]);
            u64 h2b = pack2(cBv[u]);
#pragma unroll
            for (int g = 0; g < 4; g++) {
                ulonglong2 q = *(const ulonglong2*)(xs + g * (FIN * 4) + k * 4);
                ffma2(accA[2 * g], q.x, h2a); ffma2(accA[2 * g + 1], q.y, h2a);
                ffma2(accB[2 * g], q.x, h2b); ffma2(accB[2 * g + 1], q.y, h2b);
            }
        }
    }
    const float bA = bias[c], bBv = bias[c + 128];
    float* ob = out + (size_t)row0 * HH + c;
#pragma unroll
    for (int p = 0; p < 8; p++) {
        float2 vA = unpack2(accA[p]);
        float2 vB = unpack2(accB[p]);
        ob[(size_t)(2 * p) * HH]           = vA.x + bA;
        ob[(size_t)(2 * p + 1) * HH]       = vA.y + bA;
        ob[(size_t)(2 * p) * HH + 128]     = vB.x + bBv;
        ob[(size_t)(2 * p + 1) * HH + 128] = vB.y + bBv;
    }
}

// ============================================================================
// gemm256 + fused s1/s2
// ============================================================================
__global__ __launch_bounds__(128) void gemm_s1s2_kernel(
    const float* __restrict__ X, const float* __restrict__ W,
    const float* __restrict__ a1, const float* __restrict__ a2,
    float* __restrict__ hout, float* __restrict__ s1o, float* __restrict__ s2o)
{
    __shared__ float xs[4 * HH * 4];
    __shared__ float red[128];
    const int row0 = blockIdx.x * 16;
    const int tid = threadIdx.x;
    const int lane = tid & 31, wid = tid >> 5;

#pragma unroll
    for (int it = 0; it < 8; it++) {
        int idx = it * 128 + tid;
        int g = idx >> 8, k = idx & 255;
        float4 v;
        v.x = X[(size_t)(row0 + 4 * g + 0) * HH + k];
        v.y = X[(size_t)(row0 + 4 * g + 1) * HH + k];
        v.z = X[(size_t)(row0 + 4 * g + 2) * HH + k];
        v.w = X[(size_t)(row0 + 4 * g + 3) * HH + k];
        *(float4*)(xs + g * (HH * 4) + k * 4) = v;
    }
    __syncthreads();

    u64 accA[8], accB[8];
#pragma unroll
    for (int p = 0; p < 8; p++) { accA[p] = 0ULL; accB[p] = 0ULL; }

    const int c = tid;
    float wA[4], wB[4];
#pragma unroll
    for (int u = 0; u < 4; u++) { wA[u] = W[u * HH + c]; wB[u] = W[u * HH + c + 128]; }

    for (int kt = 0; kt < HH; kt += 4) {
        float cAv[4], cBv[4];
#pragma unroll
        for (int u = 0; u < 4; u++) { cAv[u] = wA[u]; cBv[u] = wB[u]; }
        if (kt + 4 < HH) {
#pragma unroll
            for (int u = 0; u < 4; u++) {
                wA[u] = W[(kt + 4 + u) * HH + c];
                wB[u] = W[(kt + 4 + u) * HH + c + 128];
            }
        }
#pragma unroll
        for (int u = 0; u < 4; u++) {
            int k = kt + u;
            u64 h2a = pack2(cAv[u]);
            u64 h2b = pack2(cBv[u]);
#pragma unroll
            for (int g = 0; g < 4; g++) {
                ulonglong2 q = *(const ulonglong2*)(xs + g * (HH * 4) + k * 4);
                ffma2(accA[2 * g], q.x, h2a); ffma2(accA[2 * g + 1], q.y, h2a);
                ffma2(accB[2 * g], q.x, h2b); ffma2(accB[2 * g + 1], q.y, h2b);
            }
        }
    }

    const float a1A = a1[c], a1B = a1[c + 128];
    const float a2A = a2[c], a2B = a2[c + 128];
    float s1p[16], s2p[16];
    float* ob = hout + (size_t)row0 * HH + c;
#pragma unroll
    for (int p = 0; p < 8; p++) {
        float2 vA = unpack2(accA[p]);
        float2 vB = unpack2(accB[p]);
        ob[(size_t)(2 * p) * HH]           = vA.x;
        ob[(size_t)(2 * p + 1) * HH]       = vA.y;
        ob[(size_t)(2 * p) * HH + 128]     = vB.x;
        ob[(size_t)(2 * p + 1) * HH + 128] = vB.y;
        s1p[2 * p]     = vA.x * a1A + vB.x * a1B;
        s1p[2 * p + 1] = vA.y * a1A + vB.y * a1B;
        s2p[2 * p]     = vA.x * a2A + vB.x * a2B;
        s2p[2 * p + 1] = vA.y * a2A + vB.y * a2B;
    }
#pragma unroll
    for (int r = 0; r < 16; r++) {
#pragma unroll
        for (int o = 16; o; o >>= 1) {
            s1p[r] += __shfl_xor_sync(0xffffffffu, s1p[r], o);
            s2p[r] += __shfl_xor_sync(0xffffffffu, s2p[r], o);
        }
        if (lane == 0) { red[r * 4 + wid] = s1p[r]; red[64 + r * 4 + wid] = s2p[r]; }
    }
    __syncthreads();
    if (tid < 32) {
        int r = tid & 15;
        int base = (tid < 16) ? 0 : 64;
        float s = red[base + r * 4] + red[base + r * 4 + 1] + red[base + r * 4 + 2] + red[base + r * 4 + 3];
        if (tid < 16) s1o[row0 + r] = s; else s2o[row0 + r] = s;
    }
}

// ============================================================================
// attention: out = relu( softmax_row( mask( leaky(s1_i + s2_j) ) ) @ h )
// 16 rows/block, 256 threads. Phase B: warp = (8-row group) x (128-col half)
// x (512-j segment): wid = jseg*4 + rg*2 + half. Lane owns 4 consecutive
// cols. Per warp-j: 2 broadcast LDS.128 + 1 LDG.128 + 16 FFMA2. 2 partials
// per output reduced through the att smem buffer. ~70 regs -> 3 blocks/SM.
// ============================================================================
__global__ __launch_bounds__(256, 3) void att_kernel(
    const uint32_t* __restrict__ mask, const float* __restrict__ h,
    const float* __restrict__ s1, const float* __restrict__ s2,
    float* __restrict__ out)
{
    extern __shared__ float att[];        // 16384 floats (64KB); reused for partials
    __shared__ uint32_t msk[16 * 32];     // 2KB: 16 rows x 32 words
    __shared__ float red[128];            // 16 rows x 8 warps
    __shared__ float rinv[16];
    __shared__ float s2mx[8];
    __shared__ float s2max_sh;

    const int b = blockIdx.y;
    const int i0 = blockIdx.x * 16;
    const int tid = threadIdx.x;
    const int lane = tid & 31, wid = tid >> 5;

    // load this block's 16 mask rows (512 words, 256 threads -> uint2 each)
    {
        const uint2* mg = (const uint2*)(mask + ((size_t)b * NN + i0) * 32);
        ((uint2*)msk)[tid] = mg[tid];
    }

    const float* s2b = s2 + b * NN;
    float s2v[4];
    float m = -3.4e38f;
#pragma unroll
    for (int u = 0; u < 4; u++) { s2v[u] = s2b[u * 256 + tid]; m = fmaxf(m, s2v[u]); }
#pragma unroll
    for (int o = 16; o; o >>= 1) m = fmaxf(m, __shfl_xor_sync(0xffffffffu, m, o));
    if (lane == 0) s2mx[wid] = m;
    __syncthreads();
    if (tid == 0) {
        float mm = s2mx[0];
#pragma unroll
        for (int w = 1; w < 8; w++) mm = fmaxf(mm, s2mx[w]);
        s2max_sh = mm;
    }
    __syncthreads();
    const float s2max = s2max_sh;

    // -------- phase A: unnormalized probs into att, rowsum partials --------
#pragma unroll
    for (int g = 0; g < 4; g++) {
        float s1v[4], mi[4], sum[4];
#pragma unroll
        for (int q = 0; q < 4; q++) {
            s1v[q] = s1[b * NN + i0 + 4 * g + q];
            mi[q] = leaky(s1v[q] + s2max);
            sum[q] = 0.f;
        }
#pragma unroll
        for (int u = 0; u < 4; u++) {
            int j = u * 256 + tid;
            float s2j = s2v[u];
            float4 pv;
#pragma unroll
            for (int q = 0; q < 4; q++) {
                uint32_t mw = msk[(4 * g + q) * 32 + u * 8 + wid];  // broadcast LDS
                float e = leaky(s1v[q] + s2j);
                float p = ((mw >> lane) & 1u) ? __expf(e - mi[q]) : 0.f;
                ((float*)&pv)[q] = p;
                sum[q] += p;
            }
            *(float4*)(att + g * 4096 + j * 4) = pv;   // conflict-free STS.128
        }
#pragma unroll
        for (int q = 0; q < 4; q++) {
#pragma unroll
            for (int o = 16; o; o >>= 1) sum[q] += __shfl_xor_sync(0xffffffffu, sum[q], o);
            if (lane == 0) red[(4 * g + q) * 8 + wid] = sum[q];
        }
    }
    __syncthreads();
    if (tid < 16) {
        float s = 0.f;
#pragma unroll
        for (int w = 0; w < 8; w++) s += red[tid * 8 + w];
        rinv[tid] = 1.0f / s;
    }
    __syncthreads();

    // -------- phase B: partial C[8,128] per warp over its 512-j segment ----
    const int half = wid & 1;            // column half
    const int rg   = (wid >> 1) & 1;     // row group (8 rows)
    const int jseg = wid >> 2;           // j segment 0..1 (512 j each)
    const int j0 = jseg * 512;

    u64 acc[4][4];   // [row-pair][col]; rp -> rows rg*8+2rp, +1
#pragma unroll
    for (int rp = 0; rp < 4; rp++)
#pragma unroll
        for (int cc = 0; cc < 4; cc++) acc[rp][cc] = 0ULL;

    const float* hp = h + b * (NN * HH) + half * 128 + lane * 4;
    const float* a0p = att + (2 * rg) * 4096;       // quad 2rg   (rows 8rg..+3)
    const float* a1p = a0p + 4096;                  // quad 2rg+1 (rows 8rg+4..+7)

    float4 hbuf[4];
#pragma unroll
    for (int u = 0; u < 4; u++) hbuf[u] = *(const float4*)(hp + (j0 + u) * HH);

    for (int jt = j0; jt < j0 + 508; jt += 4) {
#pragma unroll
        for (int u = 0; u < 4; u++) {
            const int j = jt + u;
            float4 hv = hbuf[u];
            hbuf[u] = *(const float4*)(hp + (j + 4) * HH);
            ulonglong2 aq0 = *(const ulonglong2*)(a0p + j * 4);
            ulonglong2 aq1 = *(const ulonglong2*)(a1p + j * 4);
            u64 h0 = pack2(hv.x), h1 = pack2(hv.y), h2 = pack2(hv.z), h3 = pack2(hv.w);
            ffma2(acc[0][0], aq0.x, h0); ffma2(acc[0][1], aq0.x, h1);
            ffma2(acc[0][2], aq0.x, h2); ffma2(acc[0][3], aq0.x, h3);
            ffma2(acc[1][0], aq0.y, h0); ffma2(acc[1][1], aq0.y, h1);
            ffma2(acc[1][2], aq0.y, h2); ffma2(acc[1][3], aq0.y, h3);
            ffma2(acc[2][0], aq1.x, h0); ffma2(acc[2][1], aq1.x, h1);
            ffma2(acc[2][2], aq1.x, h2); ffma2(acc[2][3], aq1.x, h3);
            ffma2(acc[3][0], aq1.y, h0); ffma2(acc[3][1], aq1.y, h1);
            ffma2(acc[3][2], aq1.y, h2); ffma2(acc[3][3], aq1.y, h3);
        }
    }
    // tail: last 4 j (no prefetch)
#pragma unroll
    for (int u = 0; u < 4; u++) {
        const int j = j0 + 508 + u;
        float4 hv = hbuf[u];
        ulonglong2 aq0 = *(const ulonglong2*)(a0p + j * 4);
        ulonglong2 aq1 = *(const ulonglong2*)(a1p + j * 4);
        u64 h0 = pack2(hv.x), h1 = pack2(hv.y), h2 = pack2(hv.z), h3 = pack2(hv.w);
        ffma2(acc[0][0], aq0.x, h0); ffma2(acc[0][1], aq0.x, h1);
        ffma2(acc[0][2], aq0.x, h2); ffma2(acc[0][3], aq0.x, h3);
        ffma2(acc[1][0], aq0.y, h0); ffma2(acc[1][1], aq0.y, h1);
        ffma2(acc[1][2], aq0.y, h2); ffma2(acc[1][3], aq0.y, h3);
        ffma2(acc[2][0], aq1.x, h0); ffma2(acc[2][1], aq1.x, h1);
        ffma2(acc[2][2], aq1.x, h2); ffma2(acc[2][3], aq1.x, h3);
        ffma2(acc[3][0], aq1.y, h0); ffma2(acc[3][1], aq1.y, h1);
        ffma2(acc[3][2], aq1.y, h2); ffma2(acc[3][3], aq1.y, h3);
    }

    // -------- reduce 2 jseg partials through smem (reuse att) --------
    __syncthreads();   // all warps done reading att
    {
        // partials layout: part[jseg][row][col], row-major 16x256 per jseg
        float* part = att + jseg * 4096 + (rg * 8) * 256 + half * 128 + lane * 4;
#pragma unroll
        for (int rp = 0; rp < 4; rp++) {
            float2 c0 = unpack2(acc[rp][0]);
            float2 c1 = unpack2(acc[rp][1]);
            float2 c2 = unpack2(acc[rp][2]);
            float2 c3 = unpack2(acc[rp][3]);
            *(float4*)(part + (2 * rp) * 256)     = make_float4(c0.x, c1.x, c2.x, c3.x);
            *(float4*)(part + (2 * rp + 1) * 256) = make_float4(c0.y, c1.y, c2.y, c3.y);
        }
    }
    __syncthreads();

    // combine: thread handles row r = tid>>4, col-quads (tid&15) + {0,16,32,48}
    {
        const int r = tid >> 4;
        const int qbase = tid & 15;
        const float ri = rinv[r];
        float* ob = out + ((size_t)b * NN + i0 + r) * HH;
#pragma unroll
        for (int k = 0; k < 4; k++) {
            const int q = qbase + k * 16;          // quad 0..63, col = q*4
            float4 v0 = *(const float4*)(att + r * 256 + q * 4);
            float4 v1 = *(const float4*)(att + 4096 + r * 256 + q * 4);
            float4 o;
            o.x = fmaxf((v0.x + v1.x) * ri, 0.f);
            o.y = fmaxf((v0.y + v1.y) * ri, 0.f);
            o.z = fmaxf((v0.z + v1.z) * ri, 0.f);
            o.w = fmaxf((v0.w + v1.w) * ri, 0.f);
            *(float4*)(ob + q * 4) = o;
        }
    }
}

// ---------------- pooling partials: 8 segments of 128 rows ----------------
__global__ __launch_bounds__(256) void pool_partial_kernel(
    const float* __restrict__ x, float* __restrict__ pool)
{
    const int seg = blockIdx.x, b = blockIdx.y, c = threadIdx.x;
    const float* xb = x + ((size_t)b * NN + seg * 128) * HH + c;
    float s = 0.f, m = -3.4e38f;
#pragma unroll 8
    for (int n = 0; n < 128; n++) {
        float v = xb[(size_t)n * HH];
        s += v;
        m = fmaxf(m, v);
    }
    float* pb = pool + ((size_t)b * 8 + seg) * 2 * HH;
    pb[c] = s;
    pb[HH + c] = m;
}

// ---------------- combine + 2-layer MLP ----------------
__global__ __launch_bounds__(256) void mlp_kernel(
    const float* __restrict__ pool, const float* __restrict__ W1,
    const float* __restrict__ b1, const float* __restrict__ W2,
    const float* __restrict__ b2, float* __restrict__ gout)
{
    __shared__ float g0[HH];
    __shared__ float t1[HH];
    const int b = blockIdx.x, c = threadIdx.x;
    const float* pb = pool + (size_t)b * 8 * 2 * HH;

    float s = 0.f, m = -3.4e38f;
#pragma unroll
    for (int seg = 0; seg < 8; seg++) {
        s += pb[seg * 2 * HH + c];
        m = fmaxf(m, pb[seg * 2 * HH + HH + c]);
    }
    g0[c] = s * (1.0f / NN) + m;
    __syncthreads();

    float a = b1[c];
#pragma unroll 4
    for (int k = 0; k < HH; k++) a += g0[k] * W1[k * HH + c];
    t1[c] = fmaxf(a, 0.f);
    __syncthreads();

    float a2 = b2[c];
#pragma unroll 4
    for (int k = 0; k < HH; k++) a2 += t1[k] * W2[k * HH + c];
    gout[b * HH + c] = a2;
}

// ---------------- launch ----------------
extern "C" void kernel_launch(void* const* d_in, const int* in_sizes, int n_in,
                              void* d_out, int out_size)
{
    const float* nf   = (const float*)d_in[0];
    const float* adj  = (const float*)d_in[1];
    const float* embW = (const float*)d_in[2];
    const float* embB = (const float*)d_in[3];
    const float* W0   = (const float*)d_in[4];
    const float* a10  = (const float*)d_in[5];
    const float* a20  = (const float*)d_in[6];
    const float* W1   = (const float*)d_in[7];
    const float* a11  = (const float*)d_in[8];
    const float* a21  = (const float*)d_in[9];
    const float* gW1  = (const float*)d_in[10];
    const float* gb1  = (const float*)d_in[11];
    const float* gW2  = (const float*)d_in[12];
    const float* gb2  = (const float*)d_in[13];

    float* out  = (float*)d_out;
    float* xout = out;                              // [B,N,H]
    float* gout = out + (size_t)BB * NN * HH;       // [B,H]

    float *xb, *hb, *s1b, *s2b, *poolb;
    uint32_t* maskb;
    cudaGetSymbolAddress((void**)&xb,    g_x);
    cudaGetSymbolAddress((void**)&hb,    g_h);
    cudaGetSymbolAddress((void**)&s1b,   g_s1);
    cudaGetSymbolAddress((void**)&s2b,   g_s2);
    cudaGetSymbolAddress((void**)&maskb, g_mask);
    cudaGetSymbolAddress((void**)&poolb, g_pool);

    cudaFuncSetAttribute(att_kernel, cudaFuncAttributeMaxDynamicSharedMemorySize, 64 * 1024);

    const int mrows = BB * NN;
    dim3 blk128(128);

    pack_adj_kernel<<<BB * NN * NN / 256, 256>>>(adj, maskb);
    embed_kernel<<<mrows / 16, blk128>>>(nf, embW, embB, xb);

    // layer 0
    gemm_s1s2_kernel<<<mrows / 16, blk128>>>(xb, W0, a10, a20, hb, s1b, s2b);
    att_kernel<<<dim3(NN / 16, BB), 256, 64 * 1024>>>(maskb, hb, s1b, s2b, xb);

    // layer 1
    gemm_s1s2_kernel<<<mrows / 16, blk128>>>(xb, W1, a11, a21, hb, s1b, s2b);
    att_kernel<<<dim3(NN / 16, BB), 256, 64 * 1024>>>(maskb, hb, s1b, s2b, xout);

    // pooling + MLP head
    pool_partial_kernel<<<dim3(8, BB), 256>>>(xout, poolb);
    mlp_kernel<<<BB, 256>>>(poolb, gW1, gb1, gW2, gb2, gout);
}

// round 16
// speedup vs baseline: 1.3711x; 1.3711x over previous
#include <cuda_runtime.h>
#include <cstdint>

#define BB 16
#define NN 1024
#define FIN 64
#define HH 256

__device__ float g_x[BB * NN * HH];
__device__ float g_s1[BB * NN];
__device__ float g_s2[BB * NN];
__device__ uint32_t g_mask[BB * NN * (NN / 32)];
__device__ float g_pool[BB * 8 * 2 * HH];
__device__ uint32_t g_hh[BB * 16 * 8192];   // bf16-hi H tiles: [b][chunk] 256n x 128B SW128
__device__ uint32_t g_hl[BB * 16 * 8192];   // bf16-lo H tiles

typedef unsigned long long u64;

__device__ __forceinline__ u64 pack2(float x) {
    u64 r; asm("mov.b64 %0, {%1, %1};" : "=l"(r) : "f"(x)); return r;
}
__device__ __forceinline__ void ffma2(u64& d, u64 a, u64 b) {
    asm("fma.rn.f32x2 %0, %1, %2, %0;" : "+l"(d) : "l"(a), "l"(b));
}
__device__ __forceinline__ float2 unpack2(u64 v) {
    float2 r; asm("mov.b64 {%0, %1}, %2;" : "=f"(r.x), "=f"(r.y) : "l"(v)); return r;
}
__device__ __forceinline__ float leaky(float x) { return x >= 0.f ? x : 0.2f * x; }
__device__ __forceinline__ uint32_t packbf(float hi, float lo) {
    uint32_t r; asm("cvt.rn.bf16x2.f32 %0, %1, %2;" : "=r"(r) : "f"(hi), "f"(lo)); return r;
}
__device__ __forceinline__ float lowbf(uint32_t w)  { return __uint_as_float(w << 16); }
__device__ __forceinline__ float highbf(uint32_t w) { return __uint_as_float(w & 0xFFFF0000u); }
#define SWZ(b) ((uint32_t)(b) ^ (((uint32_t)(b) >> 3) & 0x70u))

__device__ __forceinline__ uint32_t smem_u32(const void* p) {
    uint32_t a;
    asm("{ .reg .u64 t; cvta.to.shared.u64 t, %1; cvt.u32.u64 %0, t; }" : "=r"(a) : "l"(p));
    return a;
}
__device__ __forceinline__ void cpa16(uint32_t dst, const void* src) {
    asm volatile("cp.async.cg.shared.global [%0], [%1], 16;" :: "r"(dst), "l"(src));
}
__device__ __forceinline__ void ldsm4(uint32_t& r0, uint32_t& r1, uint32_t& r2, uint32_t& r3, uint32_t addr) {
    asm volatile("ldmatrix.sync.aligned.m8n8.x4.shared.b16 {%0,%1,%2,%3}, [%4];"
        : "=r"(r0), "=r"(r1), "=r"(r2), "=r"(r3) : "r"(addr));
}
__device__ __forceinline__ void mma16816(float* d, const uint32_t* a, uint32_t b0, uint32_t b1) {
    asm volatile("mma.sync.aligned.m16n8k16.row.col.f32.bf16.bf16.f32 "
        "{%0,%1,%2,%3}, {%4,%5,%6,%7}, {%8,%9}, {%0,%1,%2,%3};"
        : "+f"(d[0]), "+f"(d[1]), "+f"(d[2]), "+f"(d[3])
        : "r"(a[0]), "r"(a[1]), "r"(a[2]), "r"(a[3]), "r"(b0), "r"(b1));
}

__global__ __launch_bounds__(256) void pack_adj_kernel(
    const float* __restrict__ adj, uint32_t* __restrict__ mask)
{
    const int idx = blockIdx.x * 256 + threadIdx.x;
    const unsigned bal = __ballot_sync(0xffffffffu, adj[idx] > 0.f);
    if ((threadIdx.x & 31) == 0) mask[idx >> 5] = bal;
}

__global__ __launch_bounds__(128) void embed_kernel(
    const float* __restrict__ nf, const float* __restrict__ W,
    const float* __restrict__ bias, float* __restrict__ out)
{
    __shared__ float xs[4 * FIN * 4];
    const int row0 = blockIdx.x * 16;
    const int tid = threadIdx.x;
#pragma unroll
    for (int it = 0; it < 2; it++) {
        int idx = it * 128 + tid;
        int g = idx >> 6, k = idx & 63;
        float4 v;
        v.x = nf[(size_t)(row0 + 4 * g + 0) * FIN + k];
        v.y = nf[(size_t)(row0 + 4 * g + 1) * FIN + k];
        v.z = nf[(size_t)(row0 + 4 * g + 2) * FIN + k];
        v.w = nf[(size_t)(row0 + 4 * g + 3) * FIN + k];
        *(float4*)(xs + g * (FIN * 4) + k * 4) = v;
    }
    __syncthreads();
    u64 accA[8], accB[8];
#pragma unroll
    for (int p = 0; p < 8; p++) { accA[p] = 0ULL; accB[p] = 0ULL; }
    const int c = tid;
    float wA[4], wB[4];
#pragma unroll
    for (int u = 0; u < 4; u++) { wA[u] = W[u * HH + c]; wB[u] = W[u * HH + c + 128]; }
    for (int kt = 0; kt < FIN; kt += 4) {
        float cAv[4], cBv[4];
#pragma unroll
        for (int u = 0; u < 4; u++) { cAv[u] = wA[u]; cBv[u] = wB[u]; }
        if (kt + 4 < FIN) {
#pragma unroll
            for (int u = 0; u < 4; u++) {
                wA[u] = W[(kt + 4 + u) * HH + c];
                wB[u] = W[(kt + 4 + u) * HH + c + 128];
            }
        }
#pragma unroll
        for (int u = 0; u < 4; u++) {
            u64 h2a = pack2(cAv[u]);
            u64 h2b = pack2(cBv[u]);
#pragma unroll
            for (int g = 0; g < 4; g++) {
                ulonglong2 q = *(const ulonglong2*)(xs + g * (FIN * 4) + (kt + u) * 4);
                ffma2(accA[2 * g], q.x, h2a); ffma2(accA[2 * g + 1], q.y, h2a);
                ffma2(accB[2 * g], q.x, h2b); ffma2(accB[2 * g + 1], q.y, h2b);
            }
        }
    }
    const float bA = bias[c], bBv = bias[c + 128];
    float* ob = out + (size_t)row0 * HH + c;
#pragma unroll
    for (int p = 0; p < 8; p++) {
        float2 vA = unpack2(accA[p]);
        float2 vB = unpack2(accB[p]);
        ob[(size_t)(2 * p) * HH]           = vA.x + bA;
        ob[(size_t)(2 * p + 1) * HH]       = vA.y + bA;
        ob[(size_t)(2 * p) * HH + 128]     = vB.x + bBv;
        ob[(size_t)(2 * p + 1) * HH + 128] = vB.y + bBv;
    }
}

// gemm + s1/s2; h emitted as bf16 hi/lo SW128 [n][k] tiles
__global__ __launch_bounds__(128) void gemm_s1s2_kernel(
    const float* __restrict__ X, const float* __restrict__ W,
    const float* __restrict__ a1, const float* __restrict__ a2,
    uint32_t* __restrict__ ghh, uint32_t* __restrict__ ghl,
    float* __restrict__ s1o, float* __restrict__ s2o)
{
    __shared__ float xs[4 * HH * 4];
    __shared__ float red[128];
    const int row0 = blockIdx.x * 16;
    const int tid = threadIdx.x;
    const int lane = tid & 31, wid = tid >> 5;
#pragma unroll
    for (int it = 0; it < 8; it++) {
        int idx = it * 128 + tid;
        int g = idx >> 8, k = idx & 255;
        float4 v;
        v.x = X[(size_t)(row0 + 4 * g + 0) * HH + k];
        v.y = X[(size_t)(row0 + 4 * g + 1) * HH + k];
        v.z = X[(size_t)(row0 + 4 * g + 2) * HH + k];
        v.w = X[(size_t)(row0 + 4 * g + 3) * HH + k];
        *(float4*)(xs + g * (HH * 4) + k * 4) = v;
    }
    __syncthreads();
    u64 accA[8], accB[8];
#pragma unroll
    for (int p = 0; p < 8; p++) { accA[p] = 0ULL; accB[p] = 0ULL; }
    const int c = tid;
    float wA[4], wB[4];
#pragma unroll
    for (int u = 0; u < 4; u++) { wA[u] = W[u * HH + c]; wB[u] = W[u * HH + c + 128]; }
    for (int kt = 0; kt < HH; kt += 4) {
        float cAv[4], cBv[4];
#pragma unroll
        for (int u = 0; u < 4; u++) { cAv[u] = wA[u]; cBv[u] = wB[u]; }
        if (kt + 4 < HH) {
#pragma unroll
            for (int u = 0; u < 4; u++) {
                wA[u] = W[(kt + 4 + u) * HH + c];
                wB[u] = W[(kt + 4 + u) * HH + c + 128];
            }
        }
#pragma unroll
        for (int u = 0; u < 4; u++) {
            u64 h2a = pack2(cAv[u]);
            u64 h2b = pack2(cBv[u]);
#pragma unroll
            for (int g = 0; g < 4; g++) {
                ulonglong2 q = *(const ulonglong2*)(xs + g * (HH * 4) + (kt + u) * 4);
                ffma2(accA[2 * g], q.x, h2a); ffma2(accA[2 * g + 1], q.y, h2a);
                ffma2(accB[2 * g], q.x, h2b); ffma2(accB[2 * g + 1], q.y, h2b);
            }
        }
    }
    const int b_idx = row0 >> 10;
    const int jj = row0 & 1023;
    const size_t tile = (size_t)(b_idx * 16 + (jj >> 6)) * 8192;
    const uint32_t kb0 = (uint32_t)(jj & 63) * 2u;
    const float a1A = a1[c], a1B = a1[c + 128];
    const float a2A = a2[c], a2B = a2[c + 128];
    float s1p[16], s2p[16];
    uint32_t whA[8], wlA[8], whB[8], wlB[8];
#pragma unroll
    for (int p = 0; p < 8; p++) {
        float2 vA = unpack2(accA[p]);
        float2 vB = unpack2(accB[p]);
        uint32_t w = packbf(vA.y, vA.x);
        whA[p] = w; wlA[p] = packbf(vA.y - highbf(w), vA.x - lowbf(w));
        w = packbf(vB.y, vB.x);
        whB[p] = w; wlB[p] = packbf(vB.y - highbf(w), vB.x - lowbf(w));
        s1p[2 * p]     = vA.x * a1A + vB.x * a1B;
        s1p[2 * p + 1] = vA.y * a1A + vB.y * a1B;
        s2p[2 * p]     = vA.x * a2A + vB.x * a2B;
        s2p[2 * p + 1] = vA.y * a2A + vB.y * a2B;
    }
    {
        char* th = (char*)(ghh + tile);
        char* tl = (char*)(ghl + tile);
        const uint32_t cA = (uint32_t)c * 128u + kb0;
        const uint32_t cB = (uint32_t)(c + 128) * 128u + kb0;
        *(uint4*)(th + SWZ(cA))      = make_uint4(whA[0], whA[1], whA[2], whA[3]);
        *(uint4*)(th + SWZ(cA + 16)) = make_uint4(whA[4], whA[5], whA[6], whA[7]);
        *(uint4*)(th + SWZ(cB))      = make_uint4(whB[0], whB[1], whB[2], whB[3]);
        *(uint4*)(th + SWZ(cB + 16)) = make_uint4(whB[4], whB[5], whB[6], whB[7]);
        *(uint4*)(tl + SWZ(cA))      = make_uint4(wlA[0], wlA[1], wlA[2], wlA[3]);
        *(uint4*)(tl + SWZ(cA + 16)) = make_uint4(wlA[4], wlA[5], wlA[6], wlA[7]);
        *(uint4*)(tl + SWZ(cB))      = make_uint4(wlB[0], wlB[1], wlB[2], wlB[3]);
        *(uint4*)(tl + SWZ(cB + 16)) = make_uint4(wlB[4], wlB[5], wlB[6], wlB[7]);
    }
#pragma unroll
    for (int r = 0; r < 16; r++) {
#pragma unroll
        for (int o = 16; o; o >>= 1) {
            s1p[r] += __shfl_xor_sync(0xffffffffu, s1p[r], o);
            s2p[r] += __shfl_xor_sync(0xffffffffu, s2p[r], o);
        }
        if (lane == 0) { red[r * 4 + wid] = s1p[r]; red[64 + r * 4 + wid] = s2p[r]; }
    }
    __syncthreads();
    if (tid < 32) {
        int r = tid & 15;
        int base = (tid < 16) ? 0 : 64;
        float s = red[base + r * 4] + red[base + r * 4 + 1] + red[base + r * 4 + 2] + red[base + r * 4 + 3];
        if (tid < 16) s1o[row0 + r] = s; else s2o[row0 + r] = s;
    }
}

// phase A helper: compute 8 probs for (rloc, oct), store bf16 hi/lo to P smem
__device__ __forceinline__ float phaseA_pos(
    char* dsm, const uint32_t* msk_s, const float2* s1mi,
    const float* s2b, int chunk, int pos)
{
    const int rloc = pos >> 3, oct = pos & 7;
    const int j0 = chunk * 64 + oct * 8;
    float4 q0 = *(const float4*)(s2b + j0);
    float4 q1 = *(const float4*)(s2b + j0 + 4);
    float s2a[8] = {q0.x, q0.y, q0.z, q0.w, q1.x, q1.y, q1.z, q1.w};
    const float2 sm = s1mi[rloc];
    const uint32_t mb = (msk_s[rloc * 32 + chunk * 2 + (oct >> 2)] >> ((oct & 3) * 8)) & 0xffu;
    float pv[8]; float s = 0.f;
#pragma unroll
    for (int i = 0; i < 8; i++) {
        float pe = __expf(leaky(sm.x + s2a[i]) - sm.y);
        pv[i] = ((mb >> i) & 1u) ? pe : 0.f;
        s += pv[i];
    }
    uint32_t wh[4], wl[4];
#pragma unroll
    for (int i = 0; i < 4; i++) {
        uint32_t w = packbf(pv[2 * i + 1], pv[2 * i]);
        wh[i] = w;
        wl[i] = packbf(pv[2 * i + 1] - highbf(w), pv[2 * i] - lowbf(w));
    }
    const uint32_t sw = SWZ((uint32_t)rloc * 128u + (uint32_t)oct * 16u);
    *(uint4*)(dsm + sw)         = make_uint4(wh[0], wh[1], wh[2], wh[3]);
    *(uint4*)(dsm + 16384 + sw) = make_uint4(wl[0], wl[1], wl[2], wl[3]);
    return s;
}

// mma.sync attention: C[128,256] = softmax(P)[128,1024] @ H[1024,256]
// bf16 split (PhHh + PhHl + PlHh). 512 thr, warp = (16-row tile) x (128-col half).
__global__ __launch_bounds__(512, 1) void att_mma_kernel(
    const uint32_t* __restrict__ mask,
    const uint32_t* __restrict__ hh, const uint32_t* __restrict__ hl,
    const float* __restrict__ s1, const float* __restrict__ s2,
    float* __restrict__ out)
{
    extern __shared__ char dsm[];
    // PH 0 (16K), PL 16384, HH 32768 (32K), HL 65536, MSK 98304 (16K)
    uint32_t* msk_s = (uint32_t*)(dsm + 98304);
    __shared__ float2 s1mi_s[128];
    __shared__ float rinv_s[128];
    __shared__ float redp[1024];
    __shared__ float s2red[16];
    __shared__ float s2max_sh;

    const int b = blockIdx.y;
    const int i0 = blockIdx.x * 128;
    const int tid = threadIdx.x;
    const int lane = tid & 31, w = tid >> 5;
    const int rtile = w >> 1, colh = w & 1;
    const uint32_t base = smem_u32(dsm);

    {   // H chunk 0
        const char* sh = (const char*)(hh + (size_t)(b * 16) * 8192);
        const char* sl = (const char*)(hl + (size_t)(b * 16) * 8192);
#pragma unroll
        for (int i = 0; i < 4; i++) {
            uint32_t off = (uint32_t)tid * 16u + (uint32_t)i * 8192u;
            cpa16(base + 32768u + off, sh + off);
            cpa16(base + 65536u + off, sl + off);
        }
        asm volatile("cp.async.commit_group;" ::: "memory");
    }
    {   // mask: 128 rows x 32 words = 1024 uint4
        const uint4* mg = (const uint4*)(mask + ((size_t)b * NN + i0) * 32);
        ((uint4*)msk_s)[tid] = mg[tid];
        ((uint4*)msk_s)[tid + 512] = mg[tid + 512];
    }
    const float* s2b = s2 + b * NN;
    float mx = fmaxf(s2b[tid], s2b[tid + 512]);
#pragma unroll
    for (int o = 16; o; o >>= 1) mx = fmaxf(mx, __shfl_xor_sync(0xffffffffu, mx, o));
    if (lane == 0) s2red[w] = mx;
    __syncthreads();
    if (tid == 0) {
        float mm = s2red[0];
#pragma unroll
        for (int i = 1; i < 16; i++) mm = fmaxf(mm, s2red[i]);
        s2max_sh = mm;
    }
    __syncthreads();
    if (tid < 128) {
        float sv = s1[b * NN + i0 + tid];
        s1mi_s[tid] = make_float2(sv, leaky(sv + s2max_sh));
    }
    __syncthreads();

    float acc[64];
#pragma unroll
    for (int i = 0; i < 64; i++) acc[i] = 0.f;
    float racc0 = 0.f, racc1 = 0.f;

    // ldmatrix per-lane address components
    const uint32_t a_row = (uint32_t)(rtile * 16 + (lane & 15));
    const uint32_t a_kx  = (lane & 16) ? 16u : 0u;
    const uint32_t b_row0 = (uint32_t)(colh * 128 + (lane & 7) + ((lane & 16) ? 8 : 0));
    const uint32_t b_kx  = (lane & 8) ? 16u : 0u;

    for (int c = 0; c < 16; c++) {
        racc0 += phaseA_pos(dsm, msk_s, s1mi_s, s2b, c, tid);
        racc1 += phaseA_pos(dsm, msk_s, s1mi_s, s2b, c, tid + 512);
        asm volatile("cp.async.wait_group 0;" ::: "memory");
        __syncthreads();

#pragma unroll
        for (int ks = 0; ks < 4; ks++) {
            uint32_t ah[4], al[4];
            const uint32_t aoff = a_row * 128u + (uint32_t)ks * 32u + a_kx;
            ldsm4(ah[0], ah[1], ah[2], ah[3], base + SWZ(aoff));
            ldsm4(al[0], al[1], al[2], al[3], base + 16384u + SWZ(aoff));
#pragma unroll
            for (int nt2 = 0; nt2 < 8; nt2++) {
                const uint32_t boff = (b_row0 + (uint32_t)nt2 * 16u) * 128u + (uint32_t)ks * 32u + b_kx;
                uint32_t bh0, bh1, bh2, bh3, bl0, bl1, bl2, bl3;
                ldsm4(bh0, bh1, bh2, bh3, base + 32768u + SWZ(boff));
                ldsm4(bl0, bl1, bl2, bl3, base + 65536u + SWZ(boff));
                float* ap = acc + nt2 * 8;
                mma16816(ap,     ah, bh0, bh1);
                mma16816(ap + 4, ah, bh2, bh3);
                mma16816(ap,     ah, bl0, bl1);
                mma16816(ap + 4, ah, bl2, bl3);
                mma16816(ap,     al, bh0, bh1);
                mma16816(ap + 4, al, bh2, bh3);
            }
        }
        __syncthreads();
        if (c + 1 < 16) {
            const char* sh = (const char*)(hh + (size_t)(b * 16 + c + 1) * 8192);
            const char* sl = (const char*)(hl + (size_t)(b * 16 + c + 1) * 8192);
#pragma unroll
            for (int i = 0; i < 4; i++) {
                uint32_t off = (uint32_t)tid * 16u + (uint32_t)i * 8192u;
                cpa16(base + 32768u + off, sh + off);
                cpa16(base + 65536u + off, sl + off);
            }
            asm volatile("cp.async.commit_group;" ::: "memory");
        }
    }

    redp[tid] = racc0;
    redp[tid + 512] = racc1;
    __syncthreads();
    if (tid < 128) {
        float s = 0.f;
#pragma unroll
        for (int i = 0; i < 8; i++) s += redp[tid * 8 + i];
        rinv_s[tid] = 1.0f / s;
    }
    __syncthreads();

    // epilogue: d0,d1 = row rl0 cols 2(lane&3),+1 ; d2,d3 = row rl0+8
    const int rl0 = rtile * 16 + (lane >> 2);
    const float ri0 = rinv_s[rl0], ri1 = rinv_s[rl0 + 8];
    float* ob0 = out + ((size_t)b * NN + i0 + rl0) * HH + colh * 128 + 2 * (lane & 3);
    float* ob1 = ob0 + (size_t)8 * HH;
#pragma unroll
    for (int t = 0; t < 16; t++) {
        float2 v0, v1;
        v0.x = fmaxf(acc[t * 4 + 0] * ri0, 0.f);
        v0.y = fmaxf(acc[t * 4 + 1] * ri0, 0.f);
        v1.x = fmaxf(acc[t * 4 + 2] * ri1, 0.f);
        v1.y = fmaxf(acc[t * 4 + 3] * ri1, 0.f);
        *(float2*)(ob0 + t * 8) = v0;
        *(float2*)(ob1 + t * 8) = v1;
    }
}

__global__ __launch_bounds__(256) void pool_partial_kernel(
    const float* __restrict__ x, float* __restrict__ pool)
{
    const int seg = blockIdx.x, b = blockIdx.y, c = threadIdx.x;
    const float* xb = x + ((size_t)b * NN + seg * 128) * HH + c;
    float s = 0.f, m = -3.4e38f;
#pragma unroll 8
    for (int n = 0; n < 128; n++) {
        float v = xb[(size_t)n * HH];
        s += v;
        m = fmaxf(m, v);
    }
    float* pb = pool + ((size_t)b * 8 + seg) * 2 * HH;
    pb[c] = s;
    pb[HH + c] = m;
}

__global__ __launch_bounds__(256) void mlp_kernel(
    const float* __restrict__ pool, const float* __restrict__ W1,
    const float* __restrict__ b1, const float* __restrict__ W2,
    const float* __restrict__ b2, float* __restrict__ gout)
{
    __shared__ float g0[HH];
    __shared__ float t1[HH];
    const int b = blockIdx.x, c = threadIdx.x;
    const float* pb = pool + (size_t)b * 8 * 2 * HH;
    float s = 0.f, m = -3.4e38f;
#pragma unroll
    for (int seg = 0; seg < 8; seg++) {
        s += pb[seg * 2 * HH + c];
        m = fmaxf(m, pb[seg * 2 * HH + HH + c]);
    }
    g0[c] = s * (1.0f / NN) + m;
    __syncthreads();
    float a = b1[c];
#pragma unroll 4
    for (int k = 0; k < HH; k++) a += g0[k] * W1[k * HH + c];
    t1[c] = fmaxf(a, 0.f);
    __syncthreads();
    float a2 = b2[c];
#pragma unroll 4
    for (int k = 0; k < HH; k++) a2 += t1[k] * W2[k * HH + c];
    gout[b * HH + c] = a2;
}

extern "C" void kernel_launch(void* const* d_in, const int* in_sizes, int n_in,
                              void* d_out, int out_size)
{
    const float* nf   = (const float*)d_in[0];
    const float* adj  = (const float*)d_in[1];
    const float* embW = (const float*)d_in[2];
    const float* embB = (const float*)d_in[3];
    const float* W0   = (const float*)d_in[4];
    const float* a10  = (const float*)d_in[5];
    const float* a20  = (const float*)d_in[6];
    const float* W1   = (const float*)d_in[7];
    const float* a11  = (const float*)d_in[8];
    const float* a21  = (const float*)d_in[9];
    const float* gW1  = (const float*)d_in[10];
    const float* gb1  = (const float*)d_in[11];
    const float* gW2  = (const float*)d_in[12];
    const float* gb2  = (const float*)d_in[13];

    float* out  = (float*)d_out;
    float* xout = out;
    float* gout = out + (size_t)BB * NN * HH;

    float *xb, *s1b, *s2b, *poolb;
    uint32_t *maskb, *hhb, *hlb;
    cudaGetSymbolAddress((void**)&xb,    g_x);
    cudaGetSymbolAddress((void**)&s1b,   g_s1);
    cudaGetSymbolAddress((void**)&s2b,   g_s2);
    cudaGetSymbolAddress((void**)&maskb, g_mask);
    cudaGetSymbolAddress((void**)&poolb, g_pool);
    cudaGetSymbolAddress((void**)&hhb,   g_hh);
    cudaGetSymbolAddress((void**)&hlb,   g_hl);

    const int att_smem = 114688;   // 112 KB dynamic
    cudaFuncSetAttribute(att_mma_kernel, cudaFuncAttributeMaxDynamicSharedMemorySize, att_smem);

    const int mrows = BB * NN;
    dim3 blk128(128);

    pack_adj_kernel<<<BB * NN * NN / 256, 256>>>(adj, maskb);
    embed_kernel<<<mrows / 16, blk128>>>(nf, embW, embB, xb);

    gemm_s1s2_kernel<<<mrows / 16, blk128>>>(xb, W0, a10, a20, hhb, hlb, s1b, s2b);
    att_mma_kernel<<<dim3(8, BB), 512, att_smem>>>(maskb, hhb, hlb, s1b, s2b, xb);

    gemm_s1s2_kernel<<<mrows / 16, blk128>>>(xb, W1, a11, a21, hhb, hlb, s1b, s2b);
    att_mma_kernel<<<dim3(8, BB), 512, att_smem>>>(maskb, hhb, hlb, s1b, s2b, xout);

    pool_partial_kernel<<<dim3(8, BB), 256>>>(xout, poolb);
    mlp_kernel<<<BB, 256>>>(poolb, gW1, gb1, gW2, gb2, gout);
}